// round 17
// baseline (speedup 1.0000x reference)
#include <cuda_runtime.h>
#include <cuda_bf16.h>
#include <cstdint>

#define NNODES 50000
#define NEDGES 1600000
#define MAXF   512

// ---------------- device scratch (static, no allocation) ----------------
__device__ int   g_flag;
__device__ int   g_deg[NNODES];
__device__ float g_dinv[NNODES];
__device__ float g_diag[NNODES];
__device__ int   g_rowptr[NNODES + 1];
__device__ int   g_cursor[NNODES];
__device__ int   g_ecol[NEDGES];
__device__ float g_ew[NEDGES];
__device__ float g_T1r[(size_t)NNODES * MAXF];
__device__ float g_T2r[(size_t)NNODES * MAXF];
__device__ float g_acc [(size_t)NNODES * 250];    // layer-1 y2
__device__ float g_accL[(size_t)NNODES * 1000];   // layer-2/3 GEMM partial acc
__device__ float g_v  [(size_t)NNODES * 250];     // layer-1 v
__device__ float g_h1 [(size_t)NNODES * 250];
__device__ float g_h1r[(size_t)NNODES * 250];
__device__ float g_h2 [(size_t)NNODES * 500];
__device__ float g_h2r[(size_t)NNODES * 500];
__device__ float g_xr [(size_t)NNODES * 512];
__device__ float g_W1r[3 * 512 * 250];
__device__ float g_W2r[3 * 250 * 500];
__device__ float g_W3r[3 * 500 * 1000];
// bf16 gather copies
__device__ __nv_bfloat16 g_y2b[(size_t)NNODES * 250];
__device__ __nv_bfloat16 g_T1b[(size_t)NNODES * MAXF];
__device__ __nv_bfloat16 g_h1b[(size_t)NNODES * 250];
__device__ __nv_bfloat16 g_h2b[(size_t)NNODES * 500];

__device__ __forceinline__ float to_tf32(float x) {
    float y;
    asm("cvt.rna.tf32.f32 %0, %1;" : "=f"(y) : "f"(x));
    return y;
}

// ---------------- index width detection (parallel) ----------------
__global__ void k_detect(const int* e32) {
    __shared__ int ok;
    if (threadIdx.x == 0) ok = 1;
    __syncthreads();
    if (e32[2 * threadIdx.x + 1] != 0) ok = 0;   // benign race: only writes 0
    __syncthreads();
    if (threadIdx.x == 0) g_flag = ok;
}

__device__ __forceinline__ int load_idx(const void* e, long long i) {
    if (g_flag) return (int)((const long long*)e)[i];
    return ((const int*)e)[i];
}

// ---------------- graph setup ----------------
__global__ void k_init() {
    int i = blockIdx.x * blockDim.x + threadIdx.x;
    if (i < NNODES) { g_deg[i] = 0; g_cursor[i] = 0; }
}

__global__ void k_degree(const void* e) {
    int i = blockIdx.x * blockDim.x + threadIdx.x;
    if (i < NEDGES) {
        int dst = load_idx(e, (long long)NEDGES + i);
        atomicAdd(&g_deg[dst], 1);
    }
}

__global__ void k_node() {
    int i = blockIdx.x * blockDim.x + threadIdx.x;
    if (i < NNODES) {
        int d = g_deg[i];
        g_dinv[i] = d > 0 ? rsqrtf((float)d) : 0.0f;
        g_diag[i] = d > 0 ? 0.0f : -1.0f;
    }
}

__global__ void k_scan() {
    __shared__ int warp_sums[32];
    int tid  = threadIdx.x;
    int lane = tid & 31;
    int wid  = tid >> 5;
    int carry = 0;
    for (int base = 0; base < NNODES; base += 1024) {
        int i = base + tid;
        int v = (i < NNODES) ? g_deg[i] : 0;
        int x = v;
        #pragma unroll
        for (int o = 1; o < 32; o <<= 1) {
            int y = __shfl_up_sync(0xffffffffu, x, o);
            if (lane >= o) x += y;
        }
        if (lane == 31) warp_sums[wid] = x;
        __syncthreads();
        if (tid < 32) {
            int s = warp_sums[tid];
            #pragma unroll
            for (int o = 1; o < 32; o <<= 1) {
                int y = __shfl_up_sync(0xffffffffu, s, o);
                if (tid >= o) s += y;
            }
            warp_sums[tid] = s;
        }
        __syncthreads();
        int incl = x + (wid > 0 ? warp_sums[wid - 1] : 0);
        if (i < NNODES) g_rowptr[i] = carry + incl - v;
        int total = warp_sums[31];
        __syncthreads();
        carry += total;
    }
    if (tid == 0) g_rowptr[NNODES] = carry;
}

__global__ void k_scatter(const void* e) {
    int i = blockIdx.x * blockDim.x + threadIdx.x;
    if (i < NEDGES) {
        int src = load_idx(e, i);
        int dst = load_idx(e, (long long)NEDGES + i);
        float w = -g_dinv[dst] * g_dinv[src];
        int pos = g_rowptr[dst] + atomicAdd(&g_cursor[dst], 1);
        g_ecol[pos] = src;
        g_ew[pos]   = w;
    }
}

// ---------------- rounding helper ----------------
__global__ void k_round(const float* __restrict__ in, float* __restrict__ dst, int n) {
    int i = blockIdx.x * blockDim.x + threadIdx.x;
    if (i < n) dst[i] = to_tf32(in[i]);
}

// ---------------- bf16-gather SpMM (layers 2/3) ----------
__global__ void k_spmm_b4(const uint2* __restrict__ hb, const float4* __restrict__ hs,
                          const float4* __restrict__ t0,
                          float4* __restrict__ out, float4* __restrict__ out_r,
                          uint2* __restrict__ out_b, int F4, int mode) {
    int node = blockIdx.x;
    int f = threadIdx.x;
    if (f >= F4) return;
    int s = g_rowptr[node];
    int e = g_rowptr[node + 1];
    float4 acc = make_float4(0.f, 0.f, 0.f, 0.f);
    for (int j = s; j < e; ++j) {
        int   src = __ldg(&g_ecol[j]);
        float w   = __ldg(&g_ew[j]);
        uint2 v = __ldg(&hb[(size_t)src * F4 + f]);
        __nv_bfloat162 p0 = *reinterpret_cast<const __nv_bfloat162*>(&v.x);
        __nv_bfloat162 p1 = *reinterpret_cast<const __nv_bfloat162*>(&v.y);
        float2 f0 = __bfloat1622float2(p0);
        float2 f1 = __bfloat1622float2(p1);
        acc.x = fmaf(w, f0.x, acc.x);
        acc.y = fmaf(w, f0.y, acc.y);
        acc.z = fmaf(w, f1.x, acc.z);
        acc.w = fmaf(w, f1.y, acc.w);
    }
    float dw = g_diag[node];
    float4 hv = __ldg(&hs[(size_t)node * F4 + f]);
    acc.x = fmaf(dw, hv.x, acc.x);
    acc.y = fmaf(dw, hv.y, acc.y);
    acc.z = fmaf(dw, hv.z, acc.z);
    acc.w = fmaf(dw, hv.w, acc.w);
    if (mode) {
        float4 t = __ldg(&t0[(size_t)node * F4 + f]);
        acc.x = 2.f * acc.x - t.x;
        acc.y = 2.f * acc.y - t.y;
        acc.z = 2.f * acc.z - t.z;
        acc.w = 2.f * acc.w - t.w;
    }
    size_t idx = (size_t)node * F4 + f;
    if (out) out[idx] = acc;
    if (out_r) out_r[idx] =
        make_float4(to_tf32(acc.x), to_tf32(acc.y), to_tf32(acc.z), to_tf32(acc.w));
    if (out_b) {
        __nv_bfloat162 b0 = __float22bfloat162_rn(make_float2(acc.x, acc.y));
        __nv_bfloat162 b1 = __float22bfloat162_rn(make_float2(acc.z, acc.w));
        uint2 u;
        u.x = *reinterpret_cast<uint32_t*>(&b0);
        u.y = *reinterpret_cast<uint32_t*>(&b1);
        out_b[idx] = u;
    }
}

__global__ void k_spmm_b2(const uint32_t* __restrict__ hb, const float2* __restrict__ hs,
                          const float2* __restrict__ t0,
                          float2* __restrict__ out, float2* __restrict__ out_r,
                          uint32_t* __restrict__ out_b, int F2, int mode) {
    int node = blockIdx.x;
    int f = threadIdx.x;
    if (f >= F2) return;
    int s = g_rowptr[node];
    int e = g_rowptr[node + 1];
    float2 acc = make_float2(0.f, 0.f);
    for (int j = s; j < e; ++j) {
        int   src = __ldg(&g_ecol[j]);
        float w   = __ldg(&g_ew[j]);
        uint32_t v = __ldg(&hb[(size_t)src * F2 + f]);
        float2 fv = __bfloat1622float2(*reinterpret_cast<const __nv_bfloat162*>(&v));
        acc.x = fmaf(w, fv.x, acc.x);
        acc.y = fmaf(w, fv.y, acc.y);
    }
    float dw = g_diag[node];
    float2 hv = __ldg(&hs[(size_t)node * F2 + f]);
    acc.x = fmaf(dw, hv.x, acc.x);
    acc.y = fmaf(dw, hv.y, acc.y);
    if (mode) {
        float2 t = __ldg(&t0[(size_t)node * F2 + f]);
        acc.x = 2.f * acc.x - t.x;
        acc.y = 2.f * acc.y - t.y;
    }
    size_t idx = (size_t)node * F2 + f;
    if (out) out[idx] = acc;
    if (out_r) out_r[idx] = make_float2(to_tf32(acc.x), to_tf32(acc.y));
    if (out_b) {
        __nv_bfloat162 b = __float22bfloat162_rn(acc);
        out_b[idx] = *reinterpret_cast<uint32_t*>(&b);
    }
}

// ---------------- layer-1 commuted SpMMs (250 features, vec2) ----------------
__global__ void k_l1a(const uint32_t* __restrict__ y2b, const float2* __restrict__ y2,
                      const float2* __restrict__ y1,
                      float2* __restrict__ v, uint32_t* __restrict__ vb) {
    int node = blockIdx.x;
    int f = threadIdx.x;
    if (f >= 125) return;
    int s = g_rowptr[node];
    int e = g_rowptr[node + 1];
    float2 acc = make_float2(0.f, 0.f);
    for (int j = s; j < e; ++j) {
        int   src = __ldg(&g_ecol[j]);
        float w   = __ldg(&g_ew[j]);
        uint32_t u = __ldg(&y2b[(size_t)src * 125 + f]);
        float2 fv = __bfloat1622float2(*reinterpret_cast<const __nv_bfloat162*>(&u));
        acc.x = fmaf(w, fv.x, acc.x);
        acc.y = fmaf(w, fv.y, acc.y);
    }
    size_t idx = (size_t)node * 125 + f;
    float dw = g_diag[node];
    float2 s2 = __ldg(&y2[idx]);
    acc.x = fmaf(dw, s2.x, acc.x);
    acc.y = fmaf(dw, s2.y, acc.y);
    float2 a1 = __ldg(&y1[idx]);
    float2 vv = make_float2(a1.x + 2.f * acc.x, a1.y + 2.f * acc.y);
    v[idx] = vv;
    __nv_bfloat162 b = __float22bfloat162_rn(vv);
    vb[idx] = *reinterpret_cast<uint32_t*>(&b);
}

__global__ void k_l1b(const uint32_t* __restrict__ vb, const float2* __restrict__ v,
                      const float2* __restrict__ y0, const float2* __restrict__ y2,
                      const float* __restrict__ bias,
                      float2* __restrict__ h1, float2* __restrict__ h1r,
                      uint32_t* __restrict__ h1b) {
    int node = blockIdx.x;
    int f = threadIdx.x;
    if (f >= 125) return;
    int s = g_rowptr[node];
    int e = g_rowptr[node + 1];
    float2 acc = make_float2(0.f, 0.f);
    for (int j = s; j < e; ++j) {
        int   src = __ldg(&g_ecol[j]);
        float w   = __ldg(&g_ew[j]);
        uint32_t u = __ldg(&vb[(size_t)src * 125 + f]);
        float2 fv = __bfloat1622float2(*reinterpret_cast<const __nv_bfloat162*>(&u));
        acc.x = fmaf(w, fv.x, acc.x);
        acc.y = fmaf(w, fv.y, acc.y);
    }
    size_t idx = (size_t)node * 125 + f;
    float dw = g_diag[node];
    float2 sv = __ldg(&v[idx]);
    acc.x = fmaf(dw, sv.x, acc.x);
    acc.y = fmaf(dw, sv.y, acc.y);
    float2 a0 = __ldg(&y0[idx]);
    float2 a2 = __ldg(&y2[idx]);
    float b0 = bias[2 * f], b1 = bias[2 * f + 1];
    float o0 = a0.x - a2.x + acc.x + b0;
    float o1 = a0.y - a2.y + acc.y + b1;
    o0 = o0 > 0.f ? o0 : 0.f;
    o1 = o1 > 0.f ? o1 : 0.f;
    h1[idx] = make_float2(o0, o1);
    h1r[idx] = make_float2(to_tf32(o0), to_tf32(o1));
    __nv_bfloat162 b = __float22bfloat162_rn(make_float2(o0, o1));
    h1b[idx] = *reinterpret_cast<uint32_t*>(&b);
}

// ---------------- TF32 GEMM core (R11 mainloop, unchanged) -------------------
__device__ __forceinline__ void mma_tf32(float* c, const uint32_t* a, const uint32_t* b) {
    asm volatile(
        "mma.sync.aligned.m16n8k8.row.col.f32.tf32.tf32.f32 "
        "{%0,%1,%2,%3}, {%4,%5,%6,%7}, {%8,%9}, {%0,%1,%2,%3};"
        : "+f"(c[0]), "+f"(c[1]), "+f"(c[2]), "+f"(c[3])
        : "r"(a[0]), "r"(a[1]), "r"(a[2]), "r"(a[3]), "r"(b[0]), "r"(b[1]));
}

__device__ __forceinline__ void cp_async8(uint32_t dst, const void* src, int sz) {
    asm volatile("cp.async.ca.shared.global [%0], [%1], 8, %2;"
                 :: "r"(dst), "l"(src), "r"(sz));
}
__device__ __forceinline__ void cp_commit() { asm volatile("cp.async.commit_group;"); }
template<int N> __device__ __forceinline__ void cp_wait() {
    asm volatile("cp.async.wait_group %0;" :: "n"(N));
}

#define GBM 128
#define GBN 128
#define GBK 16
#define GST 3
#define ASTRIDE 20
#define BSTRIDE 136
#define GSMEM ((GST*GBM*ASTRIDE + GST*GBK*BSTRIDE) * 4)

__device__ __forceinline__ void gemm_mainloop1(
    const float* A0, const float* W,
    int M, int K, int Nout, int bm, int bn, float acc[4][4][4])
{
    extern __shared__ float smem[];
    float* As = smem;
    float* Bs = smem + GST * GBM * ASTRIDE;
    uint32_t sA = (uint32_t)__cvta_generic_to_shared(As);
    uint32_t sB = (uint32_t)__cvta_generic_to_shared(Bs);

    int tid  = threadIdx.x;
    int wid  = tid >> 5;
    int lane = tid & 31;
    int g    = lane >> 2;
    int tig  = lane & 3;
    int wm   = wid & 1;
    int wn   = wid >> 1;

    int nt = (K + GBK - 1) / GBK;

    auto issue_tile = [&](int t) {
        int k0 = t * GBK;
        int s  = t % GST;
        #pragma unroll
        for (int q = 0; q < 4; ++q) {
            int p  = q * 256 + tid;
            int m  = p >> 3;
            int kk = (p & 7) * 2;
            int gm = bm + m, gk = k0 + kk;
            int sz = (gm < M && gk < K) ? 8 : 0;
            const float* src = sz ? (A0 + (size_t)gm * K + gk) : A0;
            uint32_t dst = sA + (uint32_t)(((s * GBM + m) * ASTRIDE + kk) * 4);
            cp_async8(dst, src, sz);
        }
        #pragma unroll
        for (int q = 0; q < 4; ++q) {
            int p  = q * 256 + tid;
            int r  = p >> 6;
            int n0 = (p & 63) * 2;
            int gk = k0 + r, gn = bn + n0;
            int sz = (gk < K && gn < Nout) ? 8 : 0;
            const float* src = sz ? (W + (size_t)gk * Nout + gn) : W;
            uint32_t dst = sB + (uint32_t)(((s * GBK + r) * BSTRIDE + n0) * 4);
            cp_async8(dst, src, sz);
        }
    };

    #pragma unroll
    for (int t = 0; t < GST - 1; ++t) {
        issue_tile(t);
        cp_commit();
    }

    for (int t = 0; t < nt; ++t) {
        cp_wait<GST - 2>();
        __syncthreads();

        int tn = t + GST - 1;
        if (tn < nt) issue_tile(tn);
        cp_commit();

        int s = t % GST;
        const float* Ab = As + s * GBM * ASTRIDE;
        const float* Bb = Bs + s * GBK * BSTRIDE;
        #pragma unroll
        for (int ks = 0; ks < GBK; ks += 8) {
            uint32_t af[4][4];
            uint32_t bf[4][2];
            #pragma unroll
            for (int mi = 0; mi < 4; ++mi) {
                int mb = wm * 64 + mi * 16;
                af[mi][0] = __float_as_uint(Ab[(mb + g    ) * ASTRIDE + ks + tig    ]);
                af[mi][1] = __float_as_uint(Ab[(mb + g + 8) * ASTRIDE + ks + tig    ]);
                af[mi][2] = __float_as_uint(Ab[(mb + g    ) * ASTRIDE + ks + tig + 4]);
                af[mi][3] = __float_as_uint(Ab[(mb + g + 8) * ASTRIDE + ks + tig + 4]);
            }
            #pragma unroll
            for (int ni = 0; ni < 4; ++ni) {
                int nb = wn * 32 + ni * 8;
                bf[ni][0] = __float_as_uint(Bb[(ks + tig    ) * BSTRIDE + nb + g]);
                bf[ni][1] = __float_as_uint(Bb[(ks + tig + 4) * BSTRIDE + nb + g]);
            }
            #pragma unroll
            for (int mi = 0; mi < 4; ++mi)
                #pragma unroll
                for (int ni = 0; ni < 4; ++ni)
                    mma_tf32(acc[mi][ni], af[mi], bf[ni]);
        }
        __syncthreads();
    }
}

// Unified single-matrix GEMM: out = A@W (+accin) (+bias -> relu + dual outputs)
__global__ __launch_bounds__(256, 2) void k_gemm1_acc(
    const float* __restrict__ A0, const float* __restrict__ W,
    const float* __restrict__ accin, const float* __restrict__ bias,
    float* __restrict__ out, float* __restrict__ out_r,
    __nv_bfloat16* __restrict__ out_b,
    int M, int K, int Nout)
{
    int bm = blockIdx.y * GBM;
    int bn = blockIdx.x * GBN;
    float acc[4][4][4];
    #pragma unroll
    for (int mi = 0; mi < 4; ++mi)
        #pragma unroll
        for (int ni = 0; ni < 4; ++ni)
            #pragma unroll
            for (int r = 0; r < 4; ++r) acc[mi][ni][r] = 0.0f;

    gemm_mainloop1(A0, W, M, K, Nout, bm, bn, acc);

    int tid  = threadIdx.x;
    int wid  = tid >> 5;
    int lane = tid & 31;
    int g    = lane >> 2;
    int tig  = lane & 3;
    int wm   = wid & 1;
    int wn   = wid >> 1;

    #pragma unroll
    for (int mi = 0; mi < 4; ++mi) {
        int r0 = bm + wm * 64 + mi * 16 + g;
        int r1 = r0 + 8;
        #pragma unroll
        for (int ni = 0; ni < 4; ++ni) {
            int c0 = bn + wn * 32 + ni * 8 + 2 * tig;
            if (c0 >= Nout) continue;
            float bv0 = bias ? bias[c0]     : 0.0f;
            float bv1 = bias ? bias[c0 + 1] : 0.0f;
            #pragma unroll
            for (int h = 0; h < 2; ++h) {
                int r = h ? r1 : r0;
                if (r >= M) continue;
                size_t o = (size_t)r * Nout + c0;
                float v0 = acc[mi][ni][2 * h]     + bv0;
                float v1 = acc[mi][ni][2 * h + 1] + bv1;
                if (accin) { v0 += accin[o]; v1 += accin[o + 1]; }
                if (bias) {
                    v0 = v0 > 0.f ? v0 : 0.f;
                    v1 = v1 > 0.f ? v1 : 0.f;
                    out[o] = v0; out[o + 1] = v1;
                    if (out_r) { out_r[o] = to_tf32(v0); out_r[o + 1] = to_tf32(v1); }
                    if (out_b) {
                        __nv_bfloat162 b = __float22bfloat162_rn(make_float2(v0, v1));
                        *reinterpret_cast<uint32_t*>(out_b + o) = *reinterpret_cast<uint32_t*>(&b);
                    }
                } else {
                    out[o] = v0; out[o + 1] = v1;
                    if (out_b) {
                        __nv_bfloat162 b = __float22bfloat162_rn(make_float2(v0, v1));
                        *reinterpret_cast<uint32_t*>(out_b + o) = *reinterpret_cast<uint32_t*>(&b);
                    }
                }
            }
        }
    }
}

// ---------------- host side ----------------
static inline int ceil_div(int a, int b) { return (a + b - 1) / b; }

extern "C" void kernel_launch(void* const* d_in, const int* in_sizes, int n_in,
                              void* d_out, int out_size) {
    const float* x  = (const float*)d_in[0];
    const void*  ei = d_in[1];
    const float* w1 = (const float*)d_in[2];
    const float* b1 = (const float*)d_in[3];
    const float* w2 = (const float*)d_in[4];
    const float* b2 = (const float*)d_in[5];
    const float* w3 = (const float*)d_in[6];
    const float* b3 = (const float*)d_in[7];
    float* out = (float*)d_out;

    // one-time host-side init (first call is the uncaptured correctness run)
    static cudaStream_t s2 = nullptr, s3 = nullptr;
    static cudaEvent_t ev[12];
    if (!s2) {
        cudaFuncSetAttribute(k_gemm1_acc, cudaFuncAttributeMaxDynamicSharedMemorySize, GSMEM);
        cudaStreamCreateWithFlags(&s2, cudaStreamNonBlocking);
        cudaStreamCreateWithFlags(&s3, cudaStreamNonBlocking);
        for (int i = 0; i < 12; ++i)
            cudaEventCreateWithFlags(&ev[i], cudaEventDisableTiming);
    }

    float *T1r, *T2r, *acc, *accL, *vbuf, *h1, *h1r, *h2, *h2r, *xr, *W1r, *W2r, *W3r;
    __nv_bfloat16 *y2b, *T1b, *h1b, *h2b;
    cudaGetSymbolAddress((void**)&T1r, g_T1r);
    cudaGetSymbolAddress((void**)&T2r, g_T2r);
    cudaGetSymbolAddress((void**)&acc, g_acc);
    cudaGetSymbolAddress((void**)&accL, g_accL);
    cudaGetSymbolAddress((void**)&vbuf, g_v);
    cudaGetSymbolAddress((void**)&h1,  g_h1);
    cudaGetSymbolAddress((void**)&h1r, g_h1r);
    cudaGetSymbolAddress((void**)&h2,  g_h2);
    cudaGetSymbolAddress((void**)&h2r, g_h2r);
    cudaGetSymbolAddress((void**)&xr,  g_xr);
    cudaGetSymbolAddress((void**)&W1r, g_W1r);
    cudaGetSymbolAddress((void**)&W2r, g_W2r);
    cudaGetSymbolAddress((void**)&W3r, g_W3r);
    cudaGetSymbolAddress((void**)&y2b, g_y2b);
    cudaGetSymbolAddress((void**)&T1b, g_T1b);
    cudaGetSymbolAddress((void**)&h1b, g_h1b);
    cudaGetSymbolAddress((void**)&h2b, g_h2b);

    cudaStream_t st0 = 0;   // capture stream (legacy default)

    // ---- fork s2: graph setup + W2/W3 rounding ----
    cudaEventRecord(ev[0], st0);
    cudaStreamWaitEvent(s2, ev[0], 0);
    k_detect<<<1, 512, 0, s2>>>((const int*)ei);
    k_init<<<ceil_div(NNODES, 256), 256, 0, s2>>>();
    k_degree<<<ceil_div(NEDGES, 256), 256, 0, s2>>>(ei);
    k_node<<<ceil_div(NNODES, 256), 256, 0, s2>>>();
    k_scan<<<1, 1024, 0, s2>>>();
    k_scatter<<<ceil_div(NEDGES, 256), 256, 0, s2>>>(ei);
    k_round<<<ceil_div(3 * 250 * 500, 256), 256, 0, s2>>>(w2, W2r, 3 * 250 * 500);
    k_round<<<ceil_div(3 * 500 * 1000, 256), 256, 0, s2>>>(w3, W3r, 3 * 500 * 1000);
    cudaEventRecord(ev[1], s2);

    // ---- st0: x/W1 rounding ----
    k_round<<<ceil_div(NNODES * 512, 256), 256, 0, st0>>>(x, xr, NNODES * 512);
    k_round<<<ceil_div(3 * 512 * 250, 256), 256, 0, st0>>>(w1, W1r, 3 * 512 * 250);
    cudaEventRecord(ev[2], st0);

    dim3 g250(ceil_div(250, GBN), ceil_div(NNODES, GBM));
    dim3 g500(ceil_div(500, GBN), ceil_div(NNODES, GBM));
    dim3 g1000(ceil_div(1000, GBN), ceil_div(NNODES, GBM));

    // ---- fork s3: gemm1(y0) ----
    cudaStreamWaitEvent(s3, ev[2], 0);
    k_gemm1_acc<<<g250, 256, GSMEM, s3>>>(xr, W1r, nullptr, nullptr,
                                          T1r, nullptr, nullptr, NNODES, 512, 250); // y0
    cudaEventRecord(ev[3], s3);

    // ---- st0: y2, y1, then commuted SpMMs ----
    k_gemm1_acc<<<g250, 256, GSMEM, st0>>>(xr, W1r + (size_t)2 * 512 * 250, nullptr, nullptr,
                                           acc, nullptr, y2b, NNODES, 512, 250);    // y2
    k_gemm1_acc<<<g250, 256, GSMEM, st0>>>(xr, W1r + (size_t)1 * 512 * 250, nullptr, nullptr,
                                           T2r, nullptr, nullptr, NNODES, 512, 250); // y1
    cudaStreamWaitEvent(st0, ev[1], 0);    // join s2: graph ready
    k_l1a<<<NNODES, 125, 0, st0>>>((const uint32_t*)y2b, (const float2*)acc,
                                   (const float2*)T2r, (float2*)vbuf, (uint32_t*)T1b);
    cudaStreamWaitEvent(st0, ev[3], 0);    // join s3: y0 ready
    k_l1b<<<NNODES, 125, 0, st0>>>((const uint32_t*)T1b, (const float2*)vbuf,
                                   (const float2*)T1r, (const float2*)acc, b1,
                                   (float2*)h1, (float2*)h1r, (uint32_t*)h1b);
    cudaEventRecord(ev[4], st0);           // h1 ready

    // ---- layer 2: spmm1/spmm2 on st0 ∥ GEMM partials on s3 ----
    k_spmm_b2<<<NNODES, 125, 0, st0>>>((const uint32_t*)h1b, (const float2*)h1, nullptr,
                                       nullptr, (float2*)T1r, (uint32_t*)T1b, 125, 0);
    cudaEventRecord(ev[5], st0);           // T1 ready
    cudaStreamWaitEvent(s3, ev[4], 0);
    k_gemm1_acc<<<g500, 256, GSMEM, s3>>>(h1r, W2r, nullptr, nullptr,
                                          accL, nullptr, nullptr, NNODES, 250, 500); // P0
    cudaStreamWaitEvent(s3, ev[5], 0);
    k_gemm1_acc<<<g500, 256, GSMEM, s3>>>(T1r, W2r + (size_t)1 * 250 * 500, accL, nullptr,
                                          accL, nullptr, nullptr, NNODES, 250, 500); // P1
    cudaEventRecord(ev[6], s3);
    k_spmm_b2<<<NNODES, 125, 0, st0>>>((const uint32_t*)T1b, (const float2*)T1r,
                                       (const float2*)h1,
                                       nullptr, (float2*)T2r, nullptr, 125, 1);
    cudaStreamWaitEvent(st0, ev[6], 0);    // join partials
    k_gemm1_acc<<<g500, 256, GSMEM, st0>>>(T2r, W2r + (size_t)2 * 250 * 500, accL, b2,
                                           h2, h2r, h2b, NNODES, 250, 500);          // P2
    cudaEventRecord(ev[7], st0);           // h2 ready

    // ---- layer 3: same pattern ----
    k_spmm_b4<<<NNODES, 125, 0, st0>>>((const uint2*)h2b, (const float4*)h2, nullptr,
                                       nullptr, (float4*)T1r, (uint2*)T1b, 125, 0);
    cudaEventRecord(ev[8], st0);           // T1 ready
    cudaStreamWaitEvent(s3, ev[7], 0);
    k_gemm1_acc<<<g1000, 256, GSMEM, s3>>>(h2r, W3r, nullptr, nullptr,
                                           accL, nullptr, nullptr, NNODES, 500, 1000); // P0
    cudaStreamWaitEvent(s3, ev[8], 0);
    k_gemm1_acc<<<g1000, 256, GSMEM, s3>>>(T1r, W3r + (size_t)1 * 500 * 1000, accL, nullptr,
                                           accL, nullptr, nullptr, NNODES, 500, 1000); // P1
    cudaEventRecord(ev[9], s3);
    k_spmm_b4<<<NNODES, 125, 0, st0>>>((const uint2*)T1b, (const float4*)T1r,
                                       (const float4*)h2,
                                       nullptr, (float4*)T2r, nullptr, 125, 1);
    cudaStreamWaitEvent(st0, ev[9], 0);    // join partials
    k_gemm1_acc<<<g1000, 256, GSMEM, st0>>>(T2r, W3r + (size_t)2 * 500 * 1000, accL, b3,
                                            out, nullptr, nullptr, NNODES, 500, 1000); // P2
}